// round 15
// baseline (speedup 1.0000x reference)
#include <cuda_runtime.h>
#include <cstdint>

#define N_NODES 500000

// Static device scratch (allocation-free rule):
// g_cs[i]  = (cos theta_i, sin theta_i)   -- 4 MB gather table
// g_acc[i] = sum over incoming edges of e^{i theta_src}  -- 4 MB accumulator
__device__ float2 g_cs[N_NODES];
__device__ float2 g_acc[N_NODES];

// ---------------------------------------------------------------------------
// Kernel 1: build (cos,sin) table, zero accumulator, and write the v output
// (v = v0*(cos,sin) -- cos/sin already in registers). Mostly hidden under
// the edge kernel's PDL prologue overlap.
// ---------------------------------------------------------------------------
__global__ void init_kernel(const float* __restrict__ theta,
                            const float* __restrict__ v0p,
                            float* __restrict__ out, int n) {
    int i = blockIdx.x * blockDim.x + threadIdx.x;
    if (i < n) {
        float v0 = __ldg(v0p);
        float sn, cs;
        __sincosf(theta[i], &sn, &cs);
        g_cs[i]  = make_float2(cs, sn);
        g_acc[i] = make_float2(0.f, 0.f);
        *((float2*)(out + 2 * i)) = make_float2(v0 * cs, v0 * sn);
    }
}

// ---------------------------------------------------------------------------
// Kernel 2: edge kernel, U=2 flat batch (8 edges/thread -- measured optimum:
// 4/iter=138us, 8=127.1us, 12=133.1us, 16=221.6us), PDL.
// sum_{e->d} e^{i(ts-td)} = e^{-i td} * sum_{e->d} e^{i ts}: per edge, gather
// only e^{i theta[src]} (8B) and RED it into acc[dst]. Index loads are
// init-independent -> issued BEFORE cudaGridDependencySynchronize(),
// overlapping init's tail. This kernel sits at the L1tex wavefront floor
// (~1 diverged gather-wf + ~1 spread REDG-lane per edge).
// ---------------------------------------------------------------------------
__global__ void __launch_bounds__(256) edge_kernel(
        const int4* __restrict__ src4,
        const int4* __restrict__ dst4,
        int n4,
        const int* __restrict__ src_tail,
        const int* __restrict__ dst_tail,
        int n_tail) {
    const int U = 2;  // int4 groups per thread => 8 edges
    int base = blockIdx.x * (blockDim.x * U) + threadIdx.x;

    int4   s[U], d[U];
    bool   ok[U];
    float2 m[U][4];

    // Phase 1: coalesced 16B index loads (do NOT depend on init's output)
    #pragma unroll
    for (int u = 0; u < U; u++) {
        int g = base + u * blockDim.x;
        ok[u] = (g < n4);
        if (ok[u]) {
            s[u] = __ldg(&src4[g]);
            d[u] = __ldg(&dst4[g]);
        }
    }

    // Wait for init_kernel's g_cs/g_acc writes before gathering.
    cudaGridDependencySynchronize();

    // Phase 2: 8 independent random gathers (front-batched MLP)
    #pragma unroll
    for (int u = 0; u < U; u++) {
        if (ok[u]) {
            m[u][0] = __ldg(&g_cs[s[u].x]);
            m[u][1] = __ldg(&g_cs[s[u].y]);
            m[u][2] = __ldg(&g_cs[s[u].z]);
            m[u][3] = __ldg(&g_cs[s[u].w]);
        }
    }

    // Phase 3: vector reductions (float2 atomicAdd -> RED .64)
    #pragma unroll
    for (int u = 0; u < U; u++) {
        if (ok[u]) {
            atomicAdd(&g_acc[d[u].x], m[u][0]);
            atomicAdd(&g_acc[d[u].y], m[u][1]);
            atomicAdd(&g_acc[d[u].z], m[u][2]);
            atomicAdd(&g_acc[d[u].w], m[u][3]);
        }
    }

    // Tail edges (n_edges % 4): spread across the grid (0 for E=16M)
    int tslot = blockIdx.x * blockDim.x + threadIdx.x;
    if (tslot < n_tail) {
        int sidx = __ldg(&src_tail[tslot]);
        int didx = __ldg(&dst_tail[tslot]);
        atomicAdd(&g_acc[didx], __ldg(&g_cs[sidx]));
    }

    // Let node_kernel start launching; its acc-reads still wait on our
    // full completion via its own cudaGridDependencySynchronize().
    cudaTriggerProgrammaticLaunchCompletion();
}

// ---------------------------------------------------------------------------
// Kernel 3: torque-only node epilogue with PDL.
// Prologue loads (g_cs from init, w0) overlap the edge kernel's tail;
// only the g_acc read requires the sync.
//   torque[i] = w0 * (c*S.y - s*S.x) / max(|S|, eps)
// (rotation by e^{-i t} preserves the norm; mean==sum under normalize)
// ---------------------------------------------------------------------------
__global__ void node_kernel(const float* __restrict__ v0p,
                            const float* __restrict__ w0p,
                            float* __restrict__ out,
                            int n) {
    int i = blockIdx.x * blockDim.x + threadIdx.x;

    float w0 = 0.f;
    float2 cs = make_float2(0.f, 0.f);
    if (i < n) {
        w0 = __ldg(w0p);
        cs = __ldg(&g_cs[i]);
    }

    // Wait for edge_kernel's atomics to be complete & visible.
    cudaGridDependencySynchronize();

    if (i < n) {
        float2 S = g_acc[i];
        float y   = cs.x * S.y - cs.y * S.x;
        float nrm = sqrtf(S.x * S.x + S.y * S.y);
        out[2 * n + i] = w0 * (y / fmaxf(nrm, 1e-12f));
    }
}

// ---------------------------------------------------------------------------
extern "C" void kernel_launch(void* const* d_in, const int* in_sizes, int n_in,
                              void* d_out, int out_size) {
    const float* theta = (const float*)d_in[0];
    const int*   src   = (const int*)d_in[1];
    const int*   dst   = (const int*)d_in[2];
    const float* v0p   = (const float*)d_in[3];
    const float* w0p   = (const float*)d_in[4];
    float*       out   = (float*)d_out;

    int n_nodes = in_sizes[0];
    int n_edges = in_sizes[1];
    int n4      = n_edges / 4;
    int n_tail  = n_edges - n4 * 4;

    // Kernel 1: plain launch
    {
        int threads = 256;
        int blocks = (n_nodes + threads - 1) / threads;
        init_kernel<<<blocks, threads>>>(theta, v0p, out, n_nodes);
    }

    // Kernel 2: PDL launch (prologue overlaps init's tail)
    {
        const int U = 2;
        int threads = 256;
        int per_block = threads * U;
        int blocks = (n4 + per_block - 1) / per_block;
        if (blocks < 1) blocks = 1;

        cudaLaunchConfig_t cfg = {};
        cfg.gridDim  = dim3((unsigned)blocks, 1, 1);
        cfg.blockDim = dim3(256, 1, 1);
        cfg.dynamicSmemBytes = 0;
        cfg.stream = 0;
        cudaLaunchAttribute attrs[1];
        attrs[0].id = cudaLaunchAttributeProgrammaticStreamSerialization;
        attrs[0].val.programmaticStreamSerializationAllowed = 1;
        cfg.attrs = attrs;
        cfg.numAttrs = 1;
        cudaLaunchKernelEx(&cfg, edge_kernel,
                           (const int4*)src, (const int4*)dst, n4,
                           (const int*)(src + n4 * 4),
                           (const int*)(dst + n4 * 4), n_tail);
    }

    // Kernel 3: PDL launch (prologue overlaps edge's tail)
    {
        int threads = 256;
        int blocks = (n_nodes + threads - 1) / threads;

        cudaLaunchConfig_t cfg = {};
        cfg.gridDim  = dim3((unsigned)blocks, 1, 1);
        cfg.blockDim = dim3((unsigned)threads, 1, 1);
        cfg.dynamicSmemBytes = 0;
        cfg.stream = 0;
        cudaLaunchAttribute attrs[1];
        attrs[0].id = cudaLaunchAttributeProgrammaticStreamSerialization;
        attrs[0].val.programmaticStreamSerializationAllowed = 1;
        cfg.attrs = attrs;
        cfg.numAttrs = 1;
        cudaLaunchKernelEx(&cfg, node_kernel, v0p, w0p, out, n_nodes);
    }
}

// round 16
// speedup vs baseline: 1.0033x; 1.0033x over previous
#include <cuda_runtime.h>
#include <cstdint>

#define N_NODES 500000

// Static device scratch (allocation-free rule):
// g_cs[i]  = (cos theta_i, sin theta_i)   -- 4 MB gather table
// g_acc[i] = sum over incoming edges of e^{i theta_src}  -- 4 MB accumulator
__device__ float2 g_cs[N_NODES];
__device__ float2 g_acc[N_NODES];

// ---------------------------------------------------------------------------
// Kernel 1: build (cos,sin) table, zero accumulator, and write the v output
// (v = v0*(cos,sin) -- cos/sin already in registers). Mostly hidden under
// the edge kernel's PDL prologue overlap.
// ---------------------------------------------------------------------------
__global__ void init_kernel(const float* __restrict__ theta,
                            const float* __restrict__ v0p,
                            float* __restrict__ out, int n) {
    int i = blockIdx.x * blockDim.x + threadIdx.x;
    if (i < n) {
        float v0 = __ldg(v0p);
        float sn, cs;
        __sincosf(theta[i], &sn, &cs);
        g_cs[i]  = make_float2(cs, sn);
        g_acc[i] = make_float2(0.f, 0.f);
        *((float2*)(out + 2 * i)) = make_float2(v0 * cs, v0 * sn);
    }
}

// ---------------------------------------------------------------------------
// Kernel 2: edge kernel, U=2 flat batch (8 edges/thread -- measured optimum:
// 4/iter=138us, 8=127.1us, 12=133.1us, 16=221.6us), PDL.
// sum_{e->d} e^{i(ts-td)} = e^{-i td} * sum_{e->d} e^{i ts}: per edge, gather
// only e^{i theta[src]} (8B) and RED it into acc[dst]. Index loads are
// init-independent -> issued BEFORE cudaGridDependencySynchronize(),
// overlapping init's tail. This kernel sits at the L1tex wavefront floor
// (~1 diverged gather-wf + ~1 spread REDG-lane per edge).
// ---------------------------------------------------------------------------
__global__ void __launch_bounds__(256) edge_kernel(
        const int4* __restrict__ src4,
        const int4* __restrict__ dst4,
        int n4,
        const int* __restrict__ src_tail,
        const int* __restrict__ dst_tail,
        int n_tail) {
    const int U = 2;  // int4 groups per thread => 8 edges
    int base = blockIdx.x * (blockDim.x * U) + threadIdx.x;

    int4   s[U], d[U];
    bool   ok[U];
    float2 m[U][4];

    // Phase 1: coalesced 16B index loads (do NOT depend on init's output)
    #pragma unroll
    for (int u = 0; u < U; u++) {
        int g = base + u * blockDim.x;
        ok[u] = (g < n4);
        if (ok[u]) {
            s[u] = __ldg(&src4[g]);
            d[u] = __ldg(&dst4[g]);
        }
    }

    // Wait for init_kernel's g_cs/g_acc writes before gathering.
    cudaGridDependencySynchronize();

    // Phase 2: 8 independent random gathers (front-batched MLP)
    #pragma unroll
    for (int u = 0; u < U; u++) {
        if (ok[u]) {
            m[u][0] = __ldg(&g_cs[s[u].x]);
            m[u][1] = __ldg(&g_cs[s[u].y]);
            m[u][2] = __ldg(&g_cs[s[u].z]);
            m[u][3] = __ldg(&g_cs[s[u].w]);
        }
    }

    // Phase 3: vector reductions (float2 atomicAdd -> RED .64)
    #pragma unroll
    for (int u = 0; u < U; u++) {
        if (ok[u]) {
            atomicAdd(&g_acc[d[u].x], m[u][0]);
            atomicAdd(&g_acc[d[u].y], m[u][1]);
            atomicAdd(&g_acc[d[u].z], m[u][2]);
            atomicAdd(&g_acc[d[u].w], m[u][3]);
        }
    }

    // Tail edges (n_edges % 4): spread across the grid (0 for E=16M)
    int tslot = blockIdx.x * blockDim.x + threadIdx.x;
    if (tslot < n_tail) {
        int sidx = __ldg(&src_tail[tslot]);
        int didx = __ldg(&dst_tail[tslot]);
        atomicAdd(&g_acc[didx], __ldg(&g_cs[sidx]));
    }

    // Let node_kernel start launching; its acc-reads still wait on our
    // full completion via its own cudaGridDependencySynchronize().
    cudaTriggerProgrammaticLaunchCompletion();
}

// ---------------------------------------------------------------------------
// Kernel 3: torque-only node epilogue with PDL.
// Prologue loads (g_cs from init, w0) overlap the edge kernel's tail;
// only the g_acc read requires the sync.
//   torque[i] = w0 * (c*S.y - s*S.x) / max(|S|, eps)
// (rotation by e^{-i t} preserves the norm; mean==sum under normalize)
// ---------------------------------------------------------------------------
__global__ void node_kernel(const float* __restrict__ v0p,
                            const float* __restrict__ w0p,
                            float* __restrict__ out,
                            int n) {
    int i = blockIdx.x * blockDim.x + threadIdx.x;

    float w0 = 0.f;
    float2 cs = make_float2(0.f, 0.f);
    if (i < n) {
        w0 = __ldg(w0p);
        cs = __ldg(&g_cs[i]);
    }

    // Wait for edge_kernel's atomics to be complete & visible.
    cudaGridDependencySynchronize();

    if (i < n) {
        float2 S = g_acc[i];
        float y   = cs.x * S.y - cs.y * S.x;
        float nrm = sqrtf(S.x * S.x + S.y * S.y);
        out[2 * n + i] = w0 * (y / fmaxf(nrm, 1e-12f));
    }
}

// ---------------------------------------------------------------------------
extern "C" void kernel_launch(void* const* d_in, const int* in_sizes, int n_in,
                              void* d_out, int out_size) {
    const float* theta = (const float*)d_in[0];
    const int*   src   = (const int*)d_in[1];
    const int*   dst   = (const int*)d_in[2];
    const float* v0p   = (const float*)d_in[3];
    const float* w0p   = (const float*)d_in[4];
    float*       out   = (float*)d_out;

    int n_nodes = in_sizes[0];
    int n_edges = in_sizes[1];
    int n4      = n_edges / 4;
    int n_tail  = n_edges - n4 * 4;

    // Kernel 1: plain launch
    {
        int threads = 256;
        int blocks = (n_nodes + threads - 1) / threads;
        init_kernel<<<blocks, threads>>>(theta, v0p, out, n_nodes);
    }

    // Kernel 2: PDL launch (prologue overlaps init's tail)
    {
        const int U = 2;
        int threads = 256;
        int per_block = threads * U;
        int blocks = (n4 + per_block - 1) / per_block;
        if (blocks < 1) blocks = 1;

        cudaLaunchConfig_t cfg = {};
        cfg.gridDim  = dim3((unsigned)blocks, 1, 1);
        cfg.blockDim = dim3(256, 1, 1);
        cfg.dynamicSmemBytes = 0;
        cfg.stream = 0;
        cudaLaunchAttribute attrs[1];
        attrs[0].id = cudaLaunchAttributeProgrammaticStreamSerialization;
        attrs[0].val.programmaticStreamSerializationAllowed = 1;
        cfg.attrs = attrs;
        cfg.numAttrs = 1;
        cudaLaunchKernelEx(&cfg, edge_kernel,
                           (const int4*)src, (const int4*)dst, n4,
                           (const int*)(src + n4 * 4),
                           (const int*)(dst + n4 * 4), n_tail);
    }

    // Kernel 3: PDL launch (prologue overlaps edge's tail)
    {
        int threads = 256;
        int blocks = (n_nodes + threads - 1) / threads;

        cudaLaunchConfig_t cfg = {};
        cfg.gridDim  = dim3((unsigned)blocks, 1, 1);
        cfg.blockDim = dim3((unsigned)threads, 1, 1);
        cfg.dynamicSmemBytes = 0;
        cfg.stream = 0;
        cudaLaunchAttribute attrs[1];
        attrs[0].id = cudaLaunchAttributeProgrammaticStreamSerialization;
        attrs[0].val.programmaticStreamSerializationAllowed = 1;
        cfg.attrs = attrs;
        cfg.numAttrs = 1;
        cudaLaunchKernelEx(&cfg, node_kernel, v0p, w0p, out, n_nodes);
    }
}